// round 5
// baseline (speedup 1.0000x reference)
#include <cuda_runtime.h>
#include <math.h>
#include <stdint.h>

#define B_   32
#define S_   64
#define T_   48
#define TD   47
#define V_   32000
#define E_   512
#define H_   1024
#define H3_  3072
#define NBLK 128

// ---------------- device scratch ----------------
__device__ float g_emb  [B_*S_*E_];
__device__ float g_demb [TD*B_*E_];
__device__ float g_gi0  [B_*S_*H3_];
__device__ float g_giemb[TD*B_*H3_];
__device__ float g_enc  [B_*S_*H_];
__device__ float g_proj [B_*S_*H_];
__device__ float g_h0   [2][B_*H_];
__device__ float g_h1   [2][B_*H_];
__device__ float g_score[B_*S_];
__device__ float g_x    [B_*H_];
__device__ float g_cat  [TD*B_*2*H_];
__device__ unsigned g_count;

__global__ void k_reset() { g_count = 0u; }

// ---------------- gathers ----------------
__global__ void k_init(const int* __restrict__ src_ids, const float* __restrict__ enc_emb)
{
    int idx = blockIdx.x * blockDim.x + threadIdx.x;
    if (idx < B_*S_*E_) {
        int m = idx >> 9, k = idx & 511;
        g_emb[idx] = enc_emb[(size_t)src_ids[m] * E_ + k];
    }
}
__global__ void k_demb(const int* __restrict__ tgt_ids, const float* __restrict__ dec_emb)
{
    int idx = blockIdx.x * blockDim.x + threadIdx.x;
    if (idx >= TD*B_*E_) return;
    int m = idx >> 9, k = idx & 511;
    int b = m & 31, t = m >> 5;
    g_demb[idx] = dec_emb[(size_t)tgt_ids[b*T_ + t] * E_ + k];
}

// ---------------- tf32 mma helpers ----------------
__device__ __forceinline__ uint32_t f2tf32(float f) {
    uint32_t u; asm("cvt.rna.tf32.f32 %0, %1;" : "=r"(u) : "f"(f)); return u;
}
__device__ __forceinline__ void mma_tf32(float c[4], const uint32_t a[4], const uint32_t b[2]) {
    asm volatile(
        "mma.sync.aligned.m16n8k8.row.col.f32.tf32.tf32.f32 "
        "{%0,%1,%2,%3}, {%4,%5,%6,%7}, {%8,%9}, {%0,%1,%2,%3};\n"
        : "+f"(c[0]), "+f"(c[1]), "+f"(c[2]), "+f"(c[3])
        : "r"(a[0]), "r"(a[1]), "r"(a[2]), "r"(a[3]), "r"(b[0]), "r"(b[1]));
}

// ---------------- grid barrier (monotonic counter; reset per replay) ----------------
__device__ __forceinline__ void gbar(unsigned &target) {
    __threadfence();
    __syncthreads();
    if (threadIdx.x == 0) {
        atomicAdd(&g_count, 1u);
        target += NBLK;
        while (*(volatile unsigned*)&g_count < target) { }
    }
    __syncthreads();
}

// ---------------- per-block GEMV pass: acc += A[32xK=1024] @ Wrows^T (3 gate groups of 8) ----
// warp w handles k in [w*128, w*128+128).  A read via ldcg (cross-block state).
__device__ __forceinline__ void gemv_pass(float acc[2][3][4],
        const float* __restrict__ A, int lda,
        const float* __restrict__ W, int ldw,
        int jt0, int lane, int warp)
{
    int g = lane >> 2, tg = lane & 3;
    int kbeg = warp * 128;
    const float* w0 = W + (size_t)(jt0 + g) * ldw;
    const float* w1 = W + (size_t)(H_ + jt0 + g) * ldw;
    const float* w2 = W + (size_t)(2*H_ + jt0 + g) * ldw;
#pragma unroll 4
    for (int kk = kbeg; kk < kbeg + 128; kk += 8) {
        uint32_t af[2][4];
#pragma unroll
        for (int mt = 0; mt < 2; mt++) {
            const float* ap = A + (size_t)(mt*16 + g) * lda + kk;
            af[mt][0] = f2tf32(__ldcg(ap + tg));
            af[mt][1] = f2tf32(__ldcg(ap + 8*lda + tg));
            af[mt][2] = f2tf32(__ldcg(ap + tg + 4));
            af[mt][3] = f2tf32(__ldcg(ap + 8*lda + tg + 4));
        }
        uint32_t bf[2];
        bf[0] = f2tf32(__ldg(w0 + kk + tg));
        bf[1] = f2tf32(__ldg(w0 + kk + tg + 4));
        mma_tf32(acc[0][0], af[0], bf);
        mma_tf32(acc[1][0], af[1], bf);
        bf[0] = f2tf32(__ldg(w1 + kk + tg));
        bf[1] = f2tf32(__ldg(w1 + kk + tg + 4));
        mma_tf32(acc[0][1], af[0], bf);
        mma_tf32(acc[1][1], af[1], bf);
        bf[0] = f2tf32(__ldg(w2 + kk + tg));
        bf[1] = f2tf32(__ldg(w2 + kk + tg + 4));
        mma_tf32(acc[0][2], af[0], bf);
        mma_tf32(acc[1][2], af[1], bf);
    }
}

// reduce 8 warps' partial C[32x24] frags -> s_out[768] (row*24+col)
__device__ __forceinline__ void reduce_acc(const float acc[2][3][4],
        float* s_red, float* s_out, int lane, int warp)
{
    int g = lane >> 2, tg = lane & 3;
#pragma unroll
    for (int mt = 0; mt < 2; mt++)
#pragma unroll
    for (int nt = 0; nt < 3; nt++)
#pragma unroll
    for (int q = 0; q < 4; q++) {
        int row = mt*16 + g + ((q >> 1) << 3);
        int col = nt*8 + 2*tg + (q & 1);
        s_red[warp*768 + row*24 + col] = acc[mt][nt][q];
    }
    __syncthreads();
    int tid = threadIdx.x;
    for (int e = tid; e < 768; e += 256) {
        float s = 0.f;
#pragma unroll
        for (int w = 0; w < 8; w++) s += s_red[w*768 + e];
        s_out[e] = s;
    }
    __syncthreads();
}

__device__ __forceinline__ float sigf(float x) { return 1.f / (1.f + expf(-x)); }

// ---------------- persistent encoder ----------------
__global__ void __launch_bounds__(256) k_enc(
    const float* __restrict__ whh0, const float* __restrict__ wih1,
    const float* __restrict__ whh1,
    const float* __restrict__ bhh0, const float* __restrict__ bih1,
    const float* __restrict__ bhh1)
{
    __shared__ float s_red[8*768];
    __shared__ float s_gi[768];
    __shared__ float s_gh[768];
    int tid = threadIdx.x, lane = tid & 31, warp = tid >> 5;
    int jt0 = blockIdx.x * 8;
    int cb = tid >> 3, cj = tid & 7;
    unsigned target = 0;

    int gidx = blockIdx.x * 256 + tid;     // 128*256 = B_*H_
    g_h0[0][gidx] = 0.f;
    g_h1[0][gidx] = 0.f;
    gbar(target);

    for (int t = 0; t < S_; t++) {
        int p = t & 1;
        // ---- layer0: gh = whh0 @ h0[p]
        float ah[2][3][4] = {};
        gemv_pass(ah, g_h0[p], H_, whh0, H_, jt0, lane, warp);
        reduce_acc(ah, s_red, s_gh, lane, warp);
        {
            int j = jt0 + cj;
            const float* gi = g_gi0 + ((size_t)cb * S_ + t) * H3_;
            float gir = gi[j], giz = gi[H_ + j], gin = gi[2*H_ + j];
            float ghr = s_gh[cb*24 + cj]      + bhh0[j];
            float ghz = s_gh[cb*24 + 8 + cj]  + bhh0[H_ + j];
            float ghn = s_gh[cb*24 + 16 + cj] + bhh0[2*H_ + j];
            float hp  = __ldcg(&g_h0[p][cb*H_ + j]);
            float r = sigf(gir + ghr);
            float z = sigf(giz + ghz);
            float n = tanhf(gin + r * ghn);
            g_h0[1-p][cb*H_ + j] = (1.f - z) * n + z * hp;
        }
        gbar(target);
        // ---- layer1: gi = wih1 @ h0[1-p], gh = whh1 @ h1[p]
        float ai[2][3][4] = {};
        float ah2[2][3][4] = {};
        gemv_pass(ai,  g_h0[1-p], H_, wih1, H_, jt0, lane, warp);
        gemv_pass(ah2, g_h1[p],   H_, whh1, H_, jt0, lane, warp);
        reduce_acc(ai,  s_red, s_gi, lane, warp);
        reduce_acc(ah2, s_red, s_gh, lane, warp);
        {
            int j = jt0 + cj;
            float gir = s_gi[cb*24 + cj]      + bih1[j];
            float giz = s_gi[cb*24 + 8 + cj]  + bih1[H_ + j];
            float gin = s_gi[cb*24 + 16 + cj] + bih1[2*H_ + j];
            float ghr = s_gh[cb*24 + cj]      + bhh1[j];
            float ghz = s_gh[cb*24 + 8 + cj]  + bhh1[H_ + j];
            float ghn = s_gh[cb*24 + 16 + cj] + bhh1[2*H_ + j];
            float hp  = __ldcg(&g_h1[p][cb*H_ + j]);
            float r = sigf(gir + ghr);
            float z = sigf(giz + ghz);
            float n = tanhf(gin + r * ghn);
            float hnew = (1.f - z) * n + z * hp;
            g_h1[1-p][cb*H_ + j] = hnew;
            g_enc[((size_t)cb * S_ + t) * H_ + j] = hnew;
        }
        gbar(target);
    }
}

// ---------------- persistent decoder ----------------
__global__ void __launch_bounds__(256) k_dec(
    const int* __restrict__ src_ids,
    const float* __restrict__ whh0, const float* __restrict__ wih0c,  // wih0c = dec_wih0+512, ldw 1536
    const float* __restrict__ wih1, const float* __restrict__ whh1,
    const float* __restrict__ bhh0, const float* __restrict__ bih1,
    const float* __restrict__ bhh1)
{
    __shared__ float s_red[8*768];
    __shared__ float s_gi[768];
    __shared__ float s_gh[768];
    __shared__ float s_sc[S_];
    __shared__ float s_ev[S_];
    __shared__ float s_mx, s_inv;
    int tid = threadIdx.x, lane = tid & 31, warp = tid >> 5;
    int jt0 = blockIdx.x * 8;
    int cb = tid >> 3, cj = tid & 7;
    int ab = blockIdx.x >> 2;                 // attn ctx batch
    int ah0 = (blockIdx.x & 3) * 256;         // attn ctx h-slice
    unsigned target = 0;

    for (int t = 0; t < TD; t++) {
        int p = t & 1;
        const float* d1p = g_h1[p];
        // ---- P1: scores
        {
            int gw = blockIdx.x * 8 + warp;
#pragma unroll
            for (int dd = 0; dd < 2; dd++) {
                int d = gw * 2 + dd;
                int b = d >> 6, s = d & 63;
                const float* pr = g_proj + ((size_t)b * S_ + s) * H_;
                const float* hv = d1p + b * H_;
                float acc = 0.f;
#pragma unroll 8
                for (int k = lane; k < H_; k += 32)
                    acc += __ldg(pr + k) * __ldcg(hv + k);
#pragma unroll
                for (int o = 16; o; o >>= 1) acc += __shfl_xor_sync(0xffffffffu, acc, o);
                if (lane == 0)
                    g_score[d] = (src_ids[b*S_ + s] != 0) ? acc : -1e9f;
            }
        }
        gbar(target);
        // ---- P2: softmax + ctx
        {
            if (tid < S_) s_sc[tid] = __ldcg(&g_score[ab*S_ + tid]);
            __syncthreads();
            if (tid == 0) {
                float mx = -1e30f;
#pragma unroll
                for (int s = 0; s < S_; s++) mx = fmaxf(mx, s_sc[s]);
                s_mx = mx;
            }
            __syncthreads();
            if (tid < S_) s_ev[tid] = expf(s_sc[tid] - s_mx);
            __syncthreads();
            if (tid == 0) {
                float su = 0.f;
#pragma unroll
                for (int s = 0; s < S_; s++) su += s_ev[s];
                s_inv = 1.f / su;
            }
            __syncthreads();
            int h = ah0 + tid;
            const float* ep = g_enc + (size_t)ab * S_ * H_ + h;
            float acc = 0.f;
#pragma unroll 8
            for (int s = 0; s < S_; s++)
                acc += s_ev[s] * __ldg(ep + (size_t)s * H_);
            acc *= s_inv;
            g_x[ab*H_ + h] = acc;
            g_cat[((size_t)t * B_ + ab) * (2*H_) + H_ + h] = acc;
        }
        gbar(target);
        // ---- P3: layer0  gi = wih0c@ctx (+giemb), gh = whh0@d0[p]
        {
            float ai[2][3][4] = {};
            float ahh[2][3][4] = {};
            gemv_pass(ai,  g_x,      H_, wih0c, E_ + H_, jt0, lane, warp);
            gemv_pass(ahh, g_h0[p],  H_, whh0,  H_,      jt0, lane, warp);
            reduce_acc(ai,  s_red, s_gi, lane, warp);
            reduce_acc(ahh, s_red, s_gh, lane, warp);
            int j = jt0 + cj;
            const float* ge = g_giemb + ((size_t)t * B_ + cb) * H3_;
            float gir = s_gi[cb*24 + cj]      + ge[j];
            float giz = s_gi[cb*24 + 8 + cj]  + ge[H_ + j];
            float gin = s_gi[cb*24 + 16 + cj] + ge[2*H_ + j];
            float ghr = s_gh[cb*24 + cj]      + bhh0[j];
            float ghz = s_gh[cb*24 + 8 + cj]  + bhh0[H_ + j];
            float ghn = s_gh[cb*24 + 16 + cj] + bhh0[2*H_ + j];
            float hp  = __ldcg(&g_h0[p][cb*H_ + j]);
            float r = sigf(gir + ghr);
            float z = sigf(giz + ghz);
            float n = tanhf(gin + r * ghn);
            g_h0[1-p][cb*H_ + j] = (1.f - z) * n + z * hp;
        }
        gbar(target);
        // ---- P4: layer1
        {
            float ai[2][3][4] = {};
            float ahh[2][3][4] = {};
            gemv_pass(ai,  g_h0[1-p], H_, wih1, H_, jt0, lane, warp);
            gemv_pass(ahh, g_h1[p],   H_, whh1, H_, jt0, lane, warp);
            reduce_acc(ai,  s_red, s_gi, lane, warp);
            reduce_acc(ahh, s_red, s_gh, lane, warp);
            int j = jt0 + cj;
            float gir = s_gi[cb*24 + cj]      + bih1[j];
            float giz = s_gi[cb*24 + 8 + cj]  + bih1[H_ + j];
            float gin = s_gi[cb*24 + 16 + cj] + bih1[2*H_ + j];
            float ghr = s_gh[cb*24 + cj]      + bhh1[j];
            float ghz = s_gh[cb*24 + 8 + cj]  + bhh1[H_ + j];
            float ghn = s_gh[cb*24 + 16 + cj] + bhh1[2*H_ + j];
            float hp  = __ldcg(&g_h1[p][cb*H_ + j]);
            float r = sigf(gir + ghr);
            float z = sigf(giz + ghz);
            float n = tanhf(gin + r * ghn);
            float hnew = (1.f - z) * n + z * hp;
            g_h1[1-p][cb*H_ + j] = hnew;
            g_cat[((size_t)t * B_ + cb) * (2*H_) + j] = hnew;
        }
        gbar(target);
    }
}

// ---------------- tf32 tensor-core GEMM (batch + output) ----------------
// mode 0: C[m*N+n]   mode 1: scatter out (B,TD,V) with m = t*B+b
__global__ __launch_bounds__(256, 2)
void k_gemm_tc(const float* __restrict__ A, int lda,
               const float* __restrict__ W, int ldw,
               const float* __restrict__ bias, float* __restrict__ C,
               int M, int N, int K, int mode)
{
    __shared__ float As[2][128*20];
    __shared__ float Bs[2][128*20];
    const int tid = threadIdx.x;
    const int m0 = blockIdx.x * 128;
    const int n0 = blockIdx.y * 128;
    const int warp = tid >> 5, lane = tid & 31;
    const int g = lane >> 2, tg = lane & 3;
    const int wm = (warp >> 2) * 64, wn = (warp & 3) * 32;

    const int lrow = tid >> 2;
    const int lk   = (tid & 3) * 4;
    int ar0 = m0 + lrow;      if (ar0 >= M) ar0 = M - 1;
    int ar1 = m0 + lrow + 64; if (ar1 >= M) ar1 = M - 1;
    const float* ag0 = A + (size_t)ar0 * lda + lk;
    const float* ag1 = A + (size_t)ar1 * lda + lk;
    const float* bg0 = W + (size_t)(n0 + lrow) * ldw + lk;
    const float* bg1 = W + (size_t)(n0 + lrow + 64) * ldw + lk;
    uint32_t sa0 = (uint32_t)__cvta_generic_to_shared(&As[0][lrow*20 + lk]);
    uint32_t sa1 = (uint32_t)__cvta_generic_to_shared(&As[0][(lrow+64)*20 + lk]);
    uint32_t sb0 = (uint32_t)__cvta_generic_to_shared(&Bs[0][lrow*20 + lk]);
    uint32_t sb1 = (uint32_t)__cvta_generic_to_shared(&Bs[0][(lrow+64)*20 + lk]);
    const uint32_t ssz = 128*20*4;

    float acc[4][4][4];
#pragma unroll
    for (int i = 0; i < 4; i++)
#pragma unroll
        for (int j = 0; j < 4; j++)
#pragma unroll
            for (int q = 0; q < 4; q++) acc[i][j][q] = 0.f;

    auto issue = [&](int st, int c) {
        uint32_t so = st ? ssz : 0;
        const float* p0 = ag0 + c*16;
        const float* p1 = ag1 + c*16;
        const float* p2 = bg0 + c*16;
        const float* p3 = bg1 + c*16;
        asm volatile("cp.async.cg.shared.global [%0], [%1], 16;\n" :: "r"(sa0+so), "l"(p0));
        asm volatile("cp.async.cg.shared.global [%0], [%1], 16;\n" :: "r"(sa1+so), "l"(p1));
        asm volatile("cp.async.cg.shared.global [%0], [%1], 16;\n" :: "r"(sb0+so), "l"(p2));
        asm volatile("cp.async.cg.shared.global [%0], [%1], 16;\n" :: "r"(sb1+so), "l"(p3));
    };

    const int nchunk = K / 16;
    issue(0, 0);
    asm volatile("cp.async.commit_group;\n");

    for (int c = 0; c < nchunk; c++) {
        if (c + 1 < nchunk) issue((c + 1) & 1, c + 1);
        asm volatile("cp.async.commit_group;\n");
        asm volatile("cp.async.wait_group 1;\n");
        __syncthreads();
        const float* as = As[c & 1];
        const float* bs = Bs[c & 1];
#pragma unroll
        for (int ks = 0; ks < 16; ks += 8) {
            uint32_t af[4][4], bf[4][2];
#pragma unroll
            for (int i = 0; i < 4; i++) {
                int r = wm + i*16 + g;
                af[i][0] = f2tf32(as[r*20 + ks + tg]);
                af[i][1] = f2tf32(as[(r+8)*20 + ks + tg]);
                af[i][2] = f2tf32(as[r*20 + ks + tg + 4]);
                af[i][3] = f2tf32(as[(r+8)*20 + ks + tg + 4]);
            }
#pragma unroll
            for (int j = 0; j < 4; j++) {
                int cc = wn + j*8 + g;
                bf[j][0] = f2tf32(bs[cc*20 + ks + tg]);
                bf[j][1] = f2tf32(bs[cc*20 + ks + tg + 4]);
            }
#pragma unroll
            for (int i = 0; i < 4; i++)
#pragma unroll
                for (int j = 0; j < 4; j++)
                    mma_tf32(acc[i][j], af[i], bf[j]);
        }
        __syncthreads();
    }

#pragma unroll
    for (int i = 0; i < 4; i++) {
#pragma unroll
        for (int j = 0; j < 4; j++) {
            int n = n0 + wn + j*8 + 2*tg;
            float bv0 = bias ? bias[n] : 0.f;
            float bv1 = bias ? bias[n + 1] : 0.f;
            int m = m0 + wm + i*16 + g;
            if (m < M) {
                float* o;
                if (mode == 0) o = C + (size_t)m * N + n;
                else {
                    int bb = m & (B_ - 1), tt = m >> 5;
                    o = C + (size_t)bb*TD*V_ + (size_t)tt*V_ + n;
                }
                o[0] = acc[i][j][0] + bv0;
                o[1] = acc[i][j][1] + bv1;
            }
            int m2 = m + 8;
            if (m2 < M) {
                float* o;
                if (mode == 0) o = C + (size_t)m2 * N + n;
                else {
                    int bb = m2 & (B_ - 1), tt = m2 >> 5;
                    o = C + (size_t)bb*TD*V_ + (size_t)tt*V_ + n;
                }
                o[0] = acc[i][j][2] + bv0;
                o[1] = acc[i][j][3] + bv1;
            }
        }
    }
}

// ---------------- host ----------------
extern "C" void kernel_launch(void* const* d_in, const int* in_sizes, int n_in,
                              void* d_out, int out_size)
{
    const int*   src_ids  = (const int*)d_in[0];
    const int*   tgt_ids  = (const int*)d_in[2];
    const float* enc_emb  = (const float*)d_in[3];
    const float* dec_emb  = (const float*)d_in[4];
    const float* enc_wih0 = (const float*)d_in[5];
    const float* enc_whh0 = (const float*)d_in[6];
    const float* enc_bih0 = (const float*)d_in[7];
    const float* enc_bhh0 = (const float*)d_in[8];
    const float* enc_wih1 = (const float*)d_in[9];
    const float* enc_whh1 = (const float*)d_in[10];
    const float* enc_bih1 = (const float*)d_in[11];
    const float* enc_bhh1 = (const float*)d_in[12];
    const float* dec_wih0 = (const float*)d_in[13];
    const float* dec_whh0 = (const float*)d_in[14];
    const float* dec_bih0 = (const float*)d_in[15];
    const float* dec_bhh0 = (const float*)d_in[16];
    const float* dec_wih1 = (const float*)d_in[17];
    const float* dec_whh1 = (const float*)d_in[18];
    const float* dec_bih1 = (const float*)d_in[19];
    const float* dec_bhh1 = (const float*)d_in[20];
    const float* attn_w   = (const float*)d_in[21];
    const float* out_w    = (const float*)d_in[22];
    const float* out_b    = (const float*)d_in[23];
    float* out = (float*)d_out;

    float *emb, *demb, *gi0, *giemb, *enc, *proj, *cat;
    cudaGetSymbolAddress((void**)&emb,   g_emb);
    cudaGetSymbolAddress((void**)&demb,  g_demb);
    cudaGetSymbolAddress((void**)&gi0,   g_gi0);
    cudaGetSymbolAddress((void**)&giemb, g_giemb);
    cudaGetSymbolAddress((void**)&enc,   g_enc);
    cudaGetSymbolAddress((void**)&proj,  g_proj);
    cudaGetSymbolAddress((void**)&cat,   g_cat);

    // gathers
    k_init<<<(B_*S_*E_ + 255)/256, 256>>>(src_ids, enc_emb);
    k_demb<<<(TD*B_*E_ + 255)/256, 256>>>(tgt_ids, dec_emb);

    // batched input-gate GEMMs (tf32)
    k_gemm_tc<<<dim3((B_*S_)/128, H3_/128), 256>>>(
        emb, E_, enc_wih0, E_, enc_bih0, gi0, B_*S_, H3_, E_, 0);
    k_gemm_tc<<<dim3((TD*B_ + 127)/128, H3_/128), 256>>>(
        demb, E_, dec_wih0, E_ + H_, dec_bih0, giemb, TD*B_, H3_, E_, 0);

    // persistent encoder
    k_reset<<<1, 1>>>();
    k_enc<<<NBLK, 256>>>(enc_whh0, enc_wih1, enc_whh1,
                         enc_bhh0, enc_bih1, enc_bhh1);

    // attention projection (tf32)
    k_gemm_tc<<<dim3((B_*S_)/128, H_/128), 256>>>(
        enc, H_, attn_w, H_, nullptr, proj, B_*S_, H_, H_, 0);

    // persistent decoder
    k_reset<<<1, 1>>>();
    k_dec<<<NBLK, 256>>>(src_ids, dec_whh0, dec_wih0 + E_,
                         dec_wih1, dec_whh1,
                         dec_bhh0, dec_bih1, dec_bhh1);

    // output projection (tf32, scatter)
    k_gemm_tc<<<dim3((TD*B_ + 127)/128, V_/128), 256>>>(
        cat, 2*H_, out_w, 2*H_, out_b, out, TD*B_, V_, 2*H_, 1);
}